// round 16
// baseline (speedup 1.0000x reference)
#include <cuda_runtime.h>
#include <math.h>

#define NSAMP  24000
#define CH     4             // samples per lane
#define SPW    128           // samples per warp (32 * 4)
#define CUTOFF 0.1f
#define OMC    0.9f          // 1 - CUTOFF
#define LN_A4  (-0.42144206f) // ln(0.9^4)
#define TSTEP  (1.0f / 23999.0f)
#define INV2PI 0.15915494309f
#define BATCH  15
#define SMEM_BYTES (2u * NSAMP * sizeof(float))

// Global scratch (device global: no allocation)
__device__ float g_trans[NSAMP];

__device__ __forceinline__ float tanh_fast(float x) {
    float e = __expf(2.0f * x);
    return 1.0f - __fdividef(2.0f, e + 1.0f);
}

// sincos for args up to ~400 rad: 2-term Cody-Waite reduction + MUFU sin/cos.
__device__ __forceinline__ void sincos_cw(float x, float* s, float* c) {
    float k = rintf(x * INV2PI);
    float r = fmaf(k, -6.28125f, x);
    r = fmaf(k, -1.9353072e-3f, r);
    *s = __sinf(r);
    *c = __cosf(r);
}

// x^20 via repeated squaring (FMA pipe, relieves MUFU).
__device__ __forceinline__ float pow20(float x) {
    float x2 = x * x, x4 = x2 * x2, x8 = x4 * x4, x16 = x8 * x8;
    return x16 * x4;
}

// Constant-coefficient inclusive scan (coefficient A4 = 0.9^4, lane-invariant).
__device__ __forceinline__ float scan_const_a4(float b, int lane) {
    const float P[5] = {0.6561f, 0.43046721f, 0.18530202f,
                        0.034336838f, 0.0011790185f};   // A4^{1,2,4,8,16}
    #pragma unroll
    for (int k = 0; k < 5; ++k) {
        int off = 1 << k;
        float bu = __shfl_up_sync(0xffffffffu, b, off);
        if (lane >= off) b = fmaf(P[k], bu, b);
    }
    return b;
}

__device__ __forceinline__ void cluster_sync() {
    asm volatile("barrier.cluster.arrive.aligned;" ::: "memory");
    asm volatile("barrier.cluster.wait.aligned;"   ::: "memory");
}

template <int NT>
__global__ __launch_bounds__(NT, 1)
void drum_synth_cluster(const float* __restrict__ p,
                        const float* __restrict__ noise_t,
                        const float* __restrict__ noise_n,
                        float* __restrict__ out)
{
    extern __shared__ float sm[];      // sre[24000]; str[24000] (generic path only)
    float* sre = sm;
    float* str = sm + NSAMP;

    const int tid  = threadIdx.x;
    const int lane = tid & 31;
    const int w    = blockIdx.x * (NT / 32) + (tid >> 5);   // global warp 0..255

    const int  s0  = w * SPW + lane * CH;
    const bool act = (s0 + CH <= NSAMP);
    const int  v0  = s0 >> 2;
    const float4* ntv = (const float4*)noise_t;

    // ---- earliest possible: prime noise_n into regs (cold DRAM) ----
    float4 nn0 = make_float4(0.f, 0.f, 0.f, 0.f);
    if (act) nn0 = ((const float4*)noise_n)[v0];

    const float decay_t  = p[1];
    const float freq_t   = p[2];
    const float sat      = p[3];
    const float gain_t   = p[4];
    const float freq_r   = p[5];
    const float feedback = p[6];
    const float gain_r   = p[7];
    const float attack_n = p[8];
    const float decay_n  = p[9];
    const float gain_n   = p[10];

    // ======== Phase A1: halo — redundantly reduce previous warp's 128 samples ====
    float hb = 0.0f;
    {
        const int hs0 = s0 - SPW;
        if (hs0 >= 0 && hs0 + CH <= NSAMP) {
            float4 x0 = ntv[hs0 >> 2];
            float y;
            y = CUTOFF * x0.x;
            y = fmaf(OMC, y, CUTOFF * x0.y);
            y = fmaf(OMC, y, CUTOFF * x0.z);
            y = fmaf(OMC, y, CUTOFF * x0.w);
            hb = y;
        }
    }
    hb = scan_const_a4(hb, lane);
    const float y_warp = __shfl_sync(0xffffffffu, hb, 31);

    // ======== Phase A2: main chunk partials from y=0 ========
    float bk[CH];
    float mb = 0.0f;
    if (act) {
        float4 x0 = ntv[v0];
        float xs[CH] = {x0.x, x0.y, x0.z, x0.w};
        float y = 0.0f;
        #pragma unroll
        for (int s = 0; s < CH; ++s) { y = fmaf(OMC, y, CUTOFF * xs[s]); bk[s] = y; }
        mb = y;
    }
    mb = scan_const_a4(mb, lane);
    float b_ie = __shfl_up_sync(0xffffffffu, mb, 1);
    if (lane == 0) b_ie = 0.0f;
    const float a_ie = __expf((float)lane * LN_A4);          // A4^lane
    const float y_in = fmaf(a_ie, y_warp, b_ie);

    // ======== Phase A3: transient via spiral/geometric recurrences ========
    float tr[CH];
    if (act) {
        const float t0 = (float)s0 * TSTEP;
        const float wf = 6.2831853f * freq_t;
        float sn, cs;
        sincos_cw(wf * t0, &sn, &cs);
        // step rotation: tiny arg -> Taylor on FMA pipe (no MUFU)
        const float xs_ = wf * TSTEP;
        const float x2_ = xs_ * xs_;
        const float sd = xs_ * fmaf(x2_, fmaf(x2_, 1.0f/120.0f, -1.0f/6.0f), 1.0f);
        const float cd = fmaf(x2_, fmaf(x2_, fmaf(x2_, -1.0f/720.0f, 1.0f/24.0f), -0.5f), 1.0f);
        const float m1 = __expf(-decay_t * TSTEP);
        const float m2 = pow20(m1);                 // exp(-20*decay*TSTEP)
        const float cdm = cd * m1, sdm = sd * m1;
        const float K  = gain_t * sat;
        const float e1 = __expf(-decay_t * t0);
        float u = sn * e1 * K;
        float v = cs * e1 * K;
        float e2g = pow20(e1) * (gain_t * 0.5f);    // exp(-20*decay*t0)*g/2
        float q   = OMC * y_in * e2g;
        const float cq = OMC * m2;
        #pragma unroll
        for (int s = 0; s < CH; ++s) {
            float sq = tanh_fast(u);
            tr[s] = sq + fmaf(bk[s], e2g, q);
            float u2 = fmaf(u, cdm,  v * sdm);
            float v2 = fmaf(v, cdm, -u * sdm);
            u = u2; v = v2;
            e2g *= m2; q *= cq;
        }
        ((float4*)g_trans)[v0] = make_float4(tr[0], tr[1], tr[2], tr[3]);
    }

    // cluster barrier: arrive=release orders g_trans stores; wait=acquire.
    cluster_sync();

    // ---- phase-C envelope setup here: overlaps chains' L2 waits ----
    const float t0c = (float)s0 * TSTEP;
    float eA = __expf(-attack_n * t0c);
    float eD = __expf(-decay_n  * t0c);
    const float a1 = __expf(-attack_n * TSTEP);
    const float d1 = __expf(-decay_n  * TSTEP);

    // ======== Phase B: resonator, REDUNDANT per CTA ========
    const float D  = 48000.0f / freq_r;
    const int   Di = (int)D;
    const bool fastp = (D >= 1.0f) && ((float)Di == D) && (Di < NSAMP);

    if (fastp) {
        // Integer delay: Di independent chains read g_trans directly from L2
        // (lane-coalesced). Full batches predicate-free with LOOKAHEAD-5:
        // y_{k+5} = fb^5 y_k + Horner(b0..b4); intermediates hang off the
        // chain as independent FMAs -> serial depth 1 FMA per 5 samples.
        const float fb  = feedback;
        const float fb2 = fb * fb;
        const float fb3 = fb2 * fb;
        const float fb4 = fb2 * fb2;
        const float fb5 = fb4 * fb;
        for (int r = tid; r < Di; r += NT) {
            float yv = g_trans[r];        // i < D => valid==0 => out = transient
            sre[r] = yv;
            int i = r + Di;
            while (i + (BATCH - 1) * Di < NSAMP) {
                float buf[BATCH];
                #pragma unroll
                for (int j = 0; j < BATCH; ++j) buf[j] = g_trans[i + j * Di];
                #pragma unroll
                for (int g = 0; g < 3; ++g) {
                    const int o = 5 * g;
                    float b0 = buf[o],   b1 = buf[o+1], b2 = buf[o+2];
                    float b3 = buf[o+3], b4 = buf[o+4];
                    float p1 = fmaf(fb, b0, b1);          // off-chain Horner
                    float p2 = fmaf(fb, p1, b2);
                    float p3 = fmaf(fb, p2, b3);
                    float p4 = fmaf(fb, p3, b4);
                    sre[i + o * Di]       = fmaf(fb,  yv, b0);
                    sre[i + (o + 1) * Di] = fmaf(fb2, yv, p1);
                    sre[i + (o + 2) * Di] = fmaf(fb3, yv, p2);
                    sre[i + (o + 3) * Di] = fmaf(fb4, yv, p3);
                    yv = fmaf(fb5, yv, p4);               // the ONLY chain FMA
                    sre[i + (o + 4) * Di] = yv;
                }
                i += BATCH * Di;
            }
            // final partial batch (loads issued in parallel, sequential consume)
            if (i < NSAMP) {
                float buf[BATCH];
                #pragma unroll
                for (int j = 0; j < BATCH; ++j) {
                    int idx = i + j * Di;
                    buf[j] = (idx < NSAMP) ? g_trans[idx] : 0.0f;
                }
                #pragma unroll
                for (int j = 0; j < BATCH; ++j) {
                    int idx = i + j * Di;
                    if (idx < NSAMP) { yv = fmaf(fb, yv, buf[j]); sre[idx] = yv; }
                }
            }
        }
        __syncthreads();
    } else {
        // Generic fractional delay: stage into smem, wave-synchronous.
        {
            const float4* tv = (const float4*)g_trans;
            float4*       sv = (float4*)str;
            for (int i4 = tid; i4 < NSAMP / 4; i4 += NT) sv[i4] = tv[i4];
        }
        for (int i = tid; i < NSAMP; i += NT) sre[i] = 0.0f;
        __syncthreads();
        if (tid == 0) sre[0] = str[0];
        int cD = (int)ceilf(D);
        int W  = min(max(cD - 1, 1), NT);
        __syncthreads();
        for (int b0 = 1; b0 < NSAMP; b0 += W) {
            const int i = b0 + tid;
            if (tid < W && i < NSAMP) {
                float delayed = (float)i - D;
                float valid   = (delayed >= 0.0f) ? 1.0f : 0.0f;
                int fl = min(max((int)floorf(delayed), 0), NSAMP - 1);
                int ce = min(fl + 1, NSAMP - 1);
                float frac = delayed - (float)fl;   // after clamp, as in reference
                float interp = (1.0f - frac) * sre[fl] + frac * sre[ce];
                sre[i] = str[i] + feedback * interp * valid;
            }
            __syncthreads();
        }
    }

    // ======== Phase C: noise envelope + final sum (tr in regs, res in smem) ====
    if (act) {
        float4 rs0 = ((const float4*)sre)[v0];
        const float nnf[CH] = {nn0.x, nn0.y, nn0.z, nn0.w};
        const float rsf[CH] = {rs0.x, rs0.y, rs0.z, rs0.w};
        float o[CH];
        float eAk = eA, eDk = eD;
        #pragma unroll
        for (int s = 0; s < CH; ++s) {
            float env = (1.0f - eAk) * eDk;
            o[s] = fmaf(nnf[s] * gain_n, env, fmaf(rsf[s], gain_r, tr[s]));
            eAk *= a1; eDk *= d1;
        }
        ((float4*)out)[v0] = make_float4(o[0], o[1], o[2], o[3]);
    }
}

extern "C" void kernel_launch(void* const* d_in, const int* in_sizes, int n_in,
                              void* d_out, int out_size)
{
    const float* params  = (const float*)d_in[0];
    const float* noise_t = (const float*)d_in[1];
    const float* noise_n = (const float*)d_in[2];
    float* out = (float*)d_out;

    cudaFuncSetAttribute(drum_synth_cluster<512>,
                         cudaFuncAttributeMaxDynamicSharedMemorySize, (int)SMEM_BYTES);
    cudaFuncSetAttribute(drum_synth_cluster<512>,
                         cudaFuncAttributeNonPortableClusterSizeAllowed, 1);

    // Preferred: 16-CTA cluster, 512 threads each (256-warp lane map).
    cudaLaunchConfig_t cfg = {};
    cfg.gridDim          = dim3(16, 1, 1);
    cfg.blockDim         = dim3(512, 1, 1);
    cfg.dynamicSmemBytes = SMEM_BYTES;
    cfg.stream           = 0;

    int maxc = 0;
    if (cudaOccupancyMaxPotentialClusterSize(&maxc, drum_synth_cluster<512>, &cfg)
        != cudaSuccess) maxc = 8;

    cudaLaunchAttribute attrs[1];
    attrs[0].id = cudaLaunchAttributeClusterDimension;

    if (maxc >= 16) {
        attrs[0].val.clusterDim = {16, 1, 1};
        cfg.attrs = attrs; cfg.numAttrs = 1;
        cudaLaunchKernelEx(&cfg, drum_synth_cluster<512>, params, noise_t, noise_n, out);
    } else {
        // Fallback: 8-CTA x 1024-thread configuration (identical lane map).
        cudaFuncSetAttribute(drum_synth_cluster<1024>,
                             cudaFuncAttributeMaxDynamicSharedMemorySize, (int)SMEM_BYTES);
        cfg.gridDim  = dim3(8, 1, 1);
        cfg.blockDim = dim3(1024, 1, 1);
        attrs[0].val.clusterDim = {8, 1, 1};
        cfg.attrs = attrs; cfg.numAttrs = 1;
        cudaLaunchKernelEx(&cfg, drum_synth_cluster<1024>, params, noise_t, noise_n, out);
    }
}